// round 14
// baseline (speedup 1.0000x reference)
#include <cuda_runtime.h>
#include <cuda_bf16.h>
#include <math.h>
#include <stdint.h>

#define BN 1024
#define QN 32768
#define DN 1024
#define TM 128          // CTA M tile
#define TN 128          // CTA N tile
#define KC 64           // K chunk (bf16 elems) = 128 bytes per row
#define NCHUNK (DN / KC)
#define NT (QN / TN)    // 256 n-tiles
#define NTHREADS 256
#define NSTAGE 3

// ---------------- device scratch (static globals; no allocation) -------------
__device__ __nv_bfloat16 g_abf[(size_t)BN * DN];
__device__ __nv_bfloat16 g_bbf[(size_t)QN * DN];
__device__ int   g_k1a[BN];
__device__ unsigned char g_act2[BN];
__device__ unsigned char g_act3[BN];
__device__ unsigned char g_pres1[32768];
__device__ unsigned char g_pres2[1024];
__device__ int   g_qinfo[QN];
__device__ float g_part[(size_t)BN * NT * 9];
__device__ float g_rowloss[3][BN];
__device__ int   g_rowpos[3][BN];

// ---------------- small PTX helpers ------------------------------------------
__device__ __forceinline__ uint32_t smem_u32(const void* p) {
    uint32_t a;
    asm("{ .reg .u64 t; cvta.to.shared.u64 t, %1; cvt.u32.u64 %0, t; }" : "=r"(a) : "l"(p));
    return a;
}
#define SW128(o) ((o) ^ (((o) >> 3) & 0x70))

__device__ __forceinline__ void cpasync16(uint32_t dst, const void* src) {
    asm volatile("cp.async.cg.shared.global [%0], [%1], 16;" :: "r"(dst), "l"(src) : "memory");
}
#define CP_COMMIT() asm volatile("cp.async.commit_group;" ::: "memory")
#define CP_WAIT0()  asm volatile("cp.async.wait_group 0;" ::: "memory")
#define CP_WAIT1()  asm volatile("cp.async.wait_group 1;" ::: "memory")

__device__ __forceinline__ void ldmx4(uint32_t* r, uint32_t addr) {
    asm volatile("ldmatrix.sync.aligned.m8n8.x4.shared.b16 {%0,%1,%2,%3}, [%4];"
                 : "=r"(r[0]), "=r"(r[1]), "=r"(r[2]), "=r"(r[3]) : "r"(addr));
}
__device__ __forceinline__ void mma16816(float* c, const uint32_t* a,
                                         uint32_t b0, uint32_t b1) {
    asm volatile(
        "mma.sync.aligned.m16n8k16.row.col.f32.bf16.bf16.f32 "
        "{%0,%1,%2,%3}, {%4,%5,%6,%7}, {%8,%9}, {%0,%1,%2,%3};"
        : "+f"(c[0]), "+f"(c[1]), "+f"(c[2]), "+f"(c[3])
        : "r"(a[0]), "r"(a[1]), "r"(a[2]), "r"(a[3]), "r"(b0), "r"(b1));
}

// ---------------- fp32 -> bf16 converters ------------------------------------
__global__ void conv_a(const float* __restrict__ in) {
    int i = blockIdx.x * blockDim.x + threadIdx.x;
    float4 v = __ldcs(&((const float4*)in)[i]);
    __nv_bfloat162 lo(__float2bfloat16(v.x), __float2bfloat16(v.y));
    __nv_bfloat162 hi(__float2bfloat16(v.z), __float2bfloat16(v.w));
    uint2 o; o.x = *(unsigned*)&lo; o.y = *(unsigned*)&hi;
    ((uint2*)g_abf)[i] = o;
}
__global__ void conv_b(const float* __restrict__ in) {
    int i = blockIdx.x * blockDim.x + threadIdx.x;
    float4 v = __ldcs(&((const float4*)in)[i]);
    __nv_bfloat162 lo(__float2bfloat16(v.x), __float2bfloat16(v.y));
    __nv_bfloat162 hi(__float2bfloat16(v.z), __float2bfloat16(v.w));
    uint2 o; o.x = *(unsigned*)&lo; o.y = *(unsigned*)&hi;
    ((uint2*)g_bbf)[i] = o;
}

// ---------------- combined anchor + queue prep (one block) --------------------
__global__ void prep_all(const int* __restrict__ labels, const int* __restrict__ lq) {
    __shared__ int sk[BN];
    __shared__ unsigned char sa2[BN];
    int i = threadIdx.x;
    for (int t = i; t < 32768; t += BN) g_pres1[t] = 0;
    g_pres2[i] = 0;
    int l0 = labels[i * 4 + 0], l1 = labels[i * 4 + 1], l2 = labels[i * 4 + 2];
    int k1 = l0 * 1024 + l1 * 32 + l2;
    sk[i] = k1;
    __syncthreads();
    bool a2 = true;
    for (int j = i + 1; j < BN; j++) if (sk[j] == k1) { a2 = false; break; }
    sa2[i] = a2 ? 1 : 0;
    __syncthreads();
    bool a3 = a2;
    if (a2) {
        int k2 = k1 >> 5;
        for (int j = 0; j < BN; j++)
            if (sa2[j] && ((sk[j] >> 5) == k2) && sk[j] > k1) { a3 = false; break; }
    }
    g_k1a[i] = k1; g_act2[i] = a2 ? 1 : 0; g_act3[i] = a3 ? 1 : 0;
    g_pres1[k1] = 1;
    if (a2) g_pres2[k1 >> 5] = 1;
    __syncthreads();   // block-scope fence: pres arrays visible to this block

    // queue info, batched 4-wide for MLP on the dependent load chains
    const int4* lq4 = (const int4*)lq;
    for (int g = 0; g < QN / BN; g += 4) {
        int qk[4];
#pragma unroll
        for (int u = 0; u < 4; u++) {
            int4 L = lq4[i + (g + u) * BN];
            qk[u] = L.x * 1024 + L.y * 32 + L.z;
        }
#pragma unroll
        for (int u = 0; u < 4; u++) {
            int qa2 = g_pres1[qk[u]] ? 0 : 1;
            int qa3 = (qa2 && !g_pres2[qk[u] >> 5]) ? 1 : 0;
            g_qinfo[i + (g + u) * BN] = qk[u] | (qa2 << 20) | (qa3 << 21);
        }
    }
}

// ---------------- fused GEMM + softmax/match partial reduction ----------------
// 3-stage cp.async pipeline: per stage A 16KB + B 16KB = 32KB; 3 stages = 96KB.
// Two CTAs co-resident per SM; wait_group 1 keeps one chunk of load slack.
#define STAGE_BYTES (TM * KC * 2 + TN * KC * 2)
static constexpr int SMEM_BYTES = NSTAGE * STAGE_BYTES + 1024;

__device__ __forceinline__ void issue_chunk(int it, int m0, int n0,
                                            uint32_t Ab, uint32_t Bb, int tid) {
    const uint4* ag = (const uint4*)g_abf;   // 128 uint4 per row
    const uint4* bg = (const uint4*)g_bbf;
    int k8 = it * (KC / 8);
#pragma unroll
    for (int u = 0; u < 4; u++) {            // A: 1024 16B chunks / 256 thr
        int idx = tid + u * NTHREADS;
        int row = idx >> 3, q = idx & 7;
        cpasync16(Ab + SW128(row * 128 + q * 16),
                  &ag[(size_t)(m0 + row) * 128 + k8 + q]);
    }
#pragma unroll
    for (int u = 0; u < 4; u++) {            // B: 1024 16B chunks / 256 thr
        int idx = tid + u * NTHREADS;
        int row = idx >> 3, q = idx & 7;
        cpasync16(Bb + SW128(row * 128 + q * 16),
                  &bg[(size_t)(n0 + row) * 128 + k8 + q]);
    }
    CP_COMMIT();
}

__global__ void __launch_bounds__(NTHREADS, 2) gemm_fused() {
    extern __shared__ char dsm[];
    char* base = (char*)(((uintptr_t)dsm + 1023) & ~(uintptr_t)1023);
    uint32_t sb = smem_u32(base);
    uint32_t Ab[NSTAGE], Bb[NSTAGE];
#pragma unroll
    for (int s = 0; s < NSTAGE; s++) {
        Ab[s] = sb + s * STAGE_BYTES;
        Bb[s] = sb + s * STAGE_BYTES + TM * KC * 2;
    }

    int tid = threadIdx.x;
    int wid = tid >> 5, lane = tid & 31;
    int m0 = blockIdx.y * TM, n0 = blockIdx.x * TN;
    int wm0 = (wid & 3) * 32;        // 4 m-warps, warp tile 32x64
    int wn0 = (wid >> 2) * 64;       // 2 n-warp groups

    float acc[2][8][4];
#pragma unroll
    for (int a = 0; a < 2; a++)
#pragma unroll
        for (int b = 0; b < 8; b++)
#pragma unroll
            for (int c = 0; c < 4; c++) acc[a][b][c] = 0.f;

    // Hoisted swizzle (k < 128 never reaches bit 7; xor term row-only)
    int akb = (lane >> 4) << 4;                       // 0 or 16
    int bkb = ((lane >> 3) & 1) << 4;                 // 0 or 16
    uint32_t a_base[2], b_base[4], a_swx[2], b_swx[4];
#pragma unroll
    for (int fm = 0; fm < 2; fm++) {
        uint32_t ro = (wm0 + fm * 16 + (lane & 15)) * 128;
        a_base[fm] = ro; a_swx[fm] = (ro >> 3) & 0x70;
    }
#pragma unroll
    for (int fn2 = 0; fn2 < 4; fn2++) {
        uint32_t ro = (wn0 + fn2 * 16 + (lane & 7) + ((lane >> 4) & 1) * 8) * 128;
        b_base[fn2] = ro; b_swx[fn2] = (ro >> 3) & 0x70;
    }

    issue_chunk(0, m0, n0, Ab[0], Bb[0], tid);
    issue_chunk(1, m0, n0, Ab[1], Bb[1], tid);
    CP_WAIT1();            // chunk 0 landed; chunk 1 may be in flight
    __syncthreads();

    for (int it = 0; it < NCHUNK; it++) {
        if (it + 2 < NCHUNK) {
            int s = (it + 2) % NSTAGE;
            issue_chunk(it + 2, m0, n0, Ab[s], Bb[s], tid);
        }
        uint32_t Abc = Ab[it % NSTAGE], Bbc = Bb[it % NSTAGE];

        // fully register-double-buffered fragments (A and B)
        uint32_t af[2][2][4], bf[2][4][4];
        ldmx4(af[0][0], Abc + a_base[0] + ((0 + akb) ^ a_swx[0]));
        ldmx4(af[0][1], Abc + a_base[1] + ((0 + akb) ^ a_swx[1]));
#pragma unroll
        for (int fn2 = 0; fn2 < 4; fn2++)
            ldmx4(bf[0][fn2], Bbc + b_base[fn2] + ((0 + bkb) ^ b_swx[fn2]));
#pragma unroll
        for (int ks = 0; ks < 4; ks++) {
            int cur = ks & 1, nxt = cur ^ 1;
            if (ks < 3) {
                uint32_t kb = (ks + 1) * 32;
                ldmx4(af[nxt][0], Abc + a_base[0] + ((kb + akb) ^ a_swx[0]));
                ldmx4(af[nxt][1], Abc + a_base[1] + ((kb + akb) ^ a_swx[1]));
#pragma unroll
                for (int fn2 = 0; fn2 < 4; fn2++)
                    ldmx4(bf[nxt][fn2], Bbc + b_base[fn2] + ((kb + bkb) ^ b_swx[fn2]));
            }
#pragma unroll
            for (int fn2 = 0; fn2 < 4; fn2++) {
                mma16816(acc[0][2 * fn2 + 0], af[cur][0], bf[cur][fn2][0], bf[cur][fn2][1]);
                mma16816(acc[0][2 * fn2 + 1], af[cur][0], bf[cur][fn2][2], bf[cur][fn2][3]);
                mma16816(acc[1][2 * fn2 + 0], af[cur][1], bf[cur][fn2][0], bf[cur][fn2][1]);
                mma16816(acc[1][2 * fn2 + 1], af[cur][1], bf[cur][fn2][2], bf[cur][fn2][3]);
            }
        }
        // next iter computes chunk it+1: require it landed; it+2 may fly
        if (it + 2 < NCHUNK) { CP_WAIT1(); } else { CP_WAIT0(); }
        __syncthreads();
    }

    // -------- epilogue: per-row 9-value partial reduction --------------------
    const float invT = 1.0f / 0.07f;
    const float LM = invT;          // analytic sim upper bound (unit vectors)

    int qv[16];
#pragma unroll
    for (int fn = 0; fn < 8; fn++)
#pragma unroll
        for (int e = 0; e < 2; e++)
            qv[fn * 2 + e] = g_qinfo[n0 + wn0 + fn * 8 + (lane & 3) * 2 + e];

    float* sacc = (float*)base;     // [2 n-warp-group][128 rows][9]
    int nw = wid >> 2;

#pragma unroll
    for (int fm = 0; fm < 2; fm++) {
#pragma unroll
        for (int half = 0; half < 2; half++) {
            int rlocal = wm0 + fm * 16 + half * 8 + (lane >> 2);
            int rglob = m0 + rlocal;
            int k1 = g_k1a[rglob];
            int a2f = g_act2[rglob], a3f = g_act3[rglob];
            int k2 = k1 >> 5, k3 = k1 >> 10;
            float S1 = 0.f, S2 = 0.f, S3 = 0.f;
            float P1 = 0.f, P2 = 0.f, P3 = 0.f;
            float c1 = 0.f, c2 = 0.f, c3 = 0.f;
#pragma unroll
            for (int fn = 0; fn < 8; fn++) {
#pragma unroll
                for (int e = 0; e < 2; e++) {
                    float s = acc[fm][fn][half * 2 + e] * invT;
                    float ex = __expf(s - LM);
                    int qi = qv[fn * 2 + e];
                    int qk = qi & 0xFFFF;
                    int qa2 = (qi >> 20) & 1, qa3 = (qi >> 21) & 1;
                    S1 += ex;
                    if (qa2) S2 += ex;
                    if (qa3) S3 += ex;
                    if (qk == k1) { P1 += s; c1 += 1.f; }
                    if (a2f && qa2 && ((qk >> 5) == k2)) { P2 += s; c2 += 1.f; }
                    if (a3f && qa3 && ((qk >> 10) == k3)) { P3 += s; c3 += 1.f; }
                }
            }
            float rs[9] = {S1, S2, S3, P1, P2, P3, c1, c2, c3};
#pragma unroll
            for (int v = 0; v < 9; v++) {
                rs[v] += __shfl_xor_sync(0xFFFFFFFFu, rs[v], 1);
                rs[v] += __shfl_xor_sync(0xFFFFFFFFu, rs[v], 2);
            }
            if ((lane & 3) == 0) {
#pragma unroll
                for (int v = 0; v < 9; v++)
                    sacc[((size_t)nw * 128 + rlocal) * 9 + v] = rs[v];
            }
        }
    }
    __syncthreads();

    for (int idx = tid; idx < 128 * 9; idx += NTHREADS) {
        int row = idx / 9, v = idx - row * 9;
        float sum = sacc[(size_t)row * 9 + v]
                  + sacc[(size_t)(128 + row) * 9 + v];
        g_part[((size_t)(m0 + row) * NT + blockIdx.x) * 9 + v] = sum;
    }
}

// ---------------- per-row final reduction ------------------------------------
__global__ void __launch_bounds__(256) row_reduce2() {
    int i = blockIdx.x;
    int t = threadIdx.x;          // one n-tile per thread (NT == 256)
    const float LM = 1.0f / 0.07f;
    float r[9];
    const float* p = &g_part[((size_t)i * NT + t) * 9];
#pragma unroll
    for (int v = 0; v < 9; v++) r[v] = p[v];
#pragma unroll
    for (int v = 0; v < 9; v++)
#pragma unroll
        for (int o = 16; o > 0; o >>= 1)
            r[v] += __shfl_xor_sync(0xFFFFFFFFu, r[v], o);

    __shared__ float wsum[8][9];
    int wid = t >> 5, lane = t & 31;
    if (lane == 0)
#pragma unroll
        for (int v = 0; v < 9; v++) wsum[wid][v] = r[v];
    __syncthreads();

    if (t == 0) {
        float res[9];
#pragma unroll
        for (int v = 0; v < 9; v++) {
            float acc = 0.f;
#pragma unroll
            for (int w = 0; w < 8; w++) acc += wsum[w][v];
            res[v] = acc;
        }
#pragma unroll
        for (int l = 0; l < 3; l++) {
            float S = res[l], P = res[3 + l], c = res[6 + l];
            float loss = 0.f;
            if (c > 0.f) loss = -(P - c * (LM + logf(S))) / (c + 1e-12f);
            g_rowloss[l][i] = loss;
            g_rowpos[l][i] = (c > 0.f) ? 1 : 0;
        }
    }
}

// ---------------- finalize ----------------------------------------------------
__global__ void __launch_bounds__(512) finalize(float* __restrict__ out) {
    __shared__ float sl[512];
    __shared__ float sn[512];
    __shared__ float layer[3];
    int t = threadIdx.x;
    for (int l = 0; l < 3; l++) {
        sl[t] = g_rowloss[l][t] + g_rowloss[l][t + 512];
        sn[t] = (float)(g_rowpos[l][t] + g_rowpos[l][t + 512]);
        __syncthreads();
        for (int s = 256; s > 0; s >>= 1) {
            if (t < s) { sl[t] += sl[t + s]; sn[t] += sn[t + s]; }
            __syncthreads();
        }
        if (t == 0) layer[l] = sl[0] / (sn[0] + 1e-12f);
        __syncthreads();
    }
    if (t == 0) {
        const float w[3] = {2.0f, 1.41421356237309515f, 1.25992104989487319f};
        float ml = -INFINITY, cum = 0.f;
#pragma unroll
        for (int l = 0; l < 3; l++) {
            float ll = fmaxf(ml, layer[l]);
            cum += w[l] * ll;
            ml = fmaxf(ml, ll);
        }
        out[0] = cum;
    }
}

// ---------------- launch ------------------------------------------------------
extern "C" void kernel_launch(void* const* d_in, const int* in_sizes, int n_in,
                              void* d_out, int out_size) {
    const float* f  = (const float*)d_in[0];
    const int*   la = (const int*)d_in[1];
    const float* fq = (const float*)d_in[2];
    const int*   lq = (const int*)d_in[3];
    float* out = (float*)d_out;

    static int attr_done = 0;
    if (!attr_done) {
        cudaFuncSetAttribute(gemm_fused, cudaFuncAttributeMaxDynamicSharedMemorySize,
                             SMEM_BYTES);
        attr_done = 1;
    }

    // order keeps gemm_fused in ncu's captured slot (-s 5 -c 1)
    conv_a<<<(BN * DN / 4) / 256, 256>>>(f);
    conv_b<<<(QN * DN / 4) / 256, 256>>>(fq);
    prep_all<<<1, BN>>>(la, lq);
    dim3 grid(QN / TN, BN / TM);
    gemm_fused<<<grid, NTHREADS, SMEM_BYTES>>>();
    row_reduce2<<<BN, 256>>>();
    finalize<<<1, 512>>>(out);
}

// round 15
// speedup vs baseline: 1.0278x; 1.0278x over previous
#include <cuda_runtime.h>
#include <cuda_bf16.h>
#include <math.h>
#include <stdint.h>

#define BN 1024
#define QN 32768
#define DN 1024
#define TM 128          // CTA M tile
#define TN 128          // CTA N tile
#define KC 64           // K chunk (bf16 elems) = 128 bytes per row
#define NCHUNK (DN / KC)
#define NT (QN / TN)    // 256 n-tiles
#define NTHREADS 256

// ---------------- device scratch (static globals; no allocation) -------------
__device__ __nv_bfloat16 g_abf[(size_t)BN * DN];
__device__ __nv_bfloat16 g_bbf[(size_t)QN * DN];
__device__ int   g_k1a[BN];
__device__ unsigned char g_act2[BN];
__device__ unsigned char g_act3[BN];
__device__ unsigned char g_pres1[32768];
__device__ unsigned char g_pres2[1024];
__device__ int   g_qinfo[QN];
__device__ float g_part[(size_t)BN * NT * 9];
__device__ float g_rowloss[3][BN];
__device__ int   g_rowpos[3][BN];

// ---------------- small PTX helpers ------------------------------------------
__device__ __forceinline__ uint32_t smem_u32(const void* p) {
    uint32_t a;
    asm("{ .reg .u64 t; cvta.to.shared.u64 t, %1; cvt.u32.u64 %0, t; }" : "=r"(a) : "l"(p));
    return a;
}
#define SW128(o) ((o) ^ (((o) >> 3) & 0x70))

__device__ __forceinline__ void cpasync16(uint32_t dst, const void* src) {
    asm volatile("cp.async.cg.shared.global [%0], [%1], 16;" :: "r"(dst), "l"(src) : "memory");
}
#define CP_COMMIT() asm volatile("cp.async.commit_group;" ::: "memory")
#define CP_WAIT0()  asm volatile("cp.async.wait_group 0;" ::: "memory")

__device__ __forceinline__ void ldmx4(uint32_t* r, uint32_t addr) {
    asm volatile("ldmatrix.sync.aligned.m8n8.x4.shared.b16 {%0,%1,%2,%3}, [%4];"
                 : "=r"(r[0]), "=r"(r[1]), "=r"(r[2]), "=r"(r[3]) : "r"(addr));
}
__device__ __forceinline__ void mma16816(float* c, const uint32_t* a,
                                         uint32_t b0, uint32_t b1) {
    asm volatile(
        "mma.sync.aligned.m16n8k16.row.col.f32.bf16.bf16.f32 "
        "{%0,%1,%2,%3}, {%4,%5,%6,%7}, {%8,%9}, {%0,%1,%2,%3};"
        : "+f"(c[0]), "+f"(c[1]), "+f"(c[2]), "+f"(c[3])
        : "r"(a[0]), "r"(a[1]), "r"(a[2]), "r"(a[3]), "r"(b0), "r"(b1));
}

// ---------------- fp32 -> bf16 converters ------------------------------------
__global__ void conv_a(const float* __restrict__ in) {
    int i = blockIdx.x * blockDim.x + threadIdx.x;
    float4 v = __ldcs(&((const float4*)in)[i]);
    __nv_bfloat162 lo(__float2bfloat16(v.x), __float2bfloat16(v.y));
    __nv_bfloat162 hi(__float2bfloat16(v.z), __float2bfloat16(v.w));
    uint2 o; o.x = *(unsigned*)&lo; o.y = *(unsigned*)&hi;
    ((uint2*)g_abf)[i] = o;
}
__global__ void conv_b(const float* __restrict__ in) {
    int i = blockIdx.x * blockDim.x + threadIdx.x;
    float4 v = __ldcs(&((const float4*)in)[i]);
    __nv_bfloat162 lo(__float2bfloat16(v.x), __float2bfloat16(v.y));
    __nv_bfloat162 hi(__float2bfloat16(v.z), __float2bfloat16(v.w));
    uint2 o; o.x = *(unsigned*)&lo; o.y = *(unsigned*)&hi;
    ((uint2*)g_bbf)[i] = o;
}

// ---------------- combined anchor + queue prep (one block) --------------------
__global__ void prep_all(const int* __restrict__ labels, const int* __restrict__ lq) {
    __shared__ int sk[BN];
    __shared__ unsigned char sa2[BN];
    int i = threadIdx.x;
    for (int t = i; t < 32768; t += BN) g_pres1[t] = 0;
    g_pres2[i] = 0;
    int l0 = labels[i * 4 + 0], l1 = labels[i * 4 + 1], l2 = labels[i * 4 + 2];
    int k1 = l0 * 1024 + l1 * 32 + l2;
    sk[i] = k1;
    __syncthreads();
    bool a2 = true;
    for (int j = i + 1; j < BN; j++) if (sk[j] == k1) { a2 = false; break; }
    sa2[i] = a2 ? 1 : 0;
    __syncthreads();
    bool a3 = a2;
    if (a2) {
        int k2 = k1 >> 5;
        for (int j = 0; j < BN; j++)
            if (sa2[j] && ((sk[j] >> 5) == k2) && sk[j] > k1) { a3 = false; break; }
    }
    g_k1a[i] = k1; g_act2[i] = a2 ? 1 : 0; g_act3[i] = a3 ? 1 : 0;
    g_pres1[k1] = 1;
    if (a2) g_pres2[k1 >> 5] = 1;
    __syncthreads();   // block-scope fence: pres arrays visible to this block

    // queue info, batched 4-wide for MLP on the dependent load chains
    const int4* lq4 = (const int4*)lq;
    for (int g = 0; g < QN / BN; g += 4) {
        int qk[4];
#pragma unroll
        for (int u = 0; u < 4; u++) {
            int4 L = lq4[i + (g + u) * BN];
            qk[u] = L.x * 1024 + L.y * 32 + L.z;
        }
#pragma unroll
        for (int u = 0; u < 4; u++) {
            int qa2 = g_pres1[qk[u]] ? 0 : 1;
            int qa3 = (qa2 && !g_pres2[qk[u] >> 5]) ? 1 : 0;
            g_qinfo[i + (g + u) * BN] = qk[u] | (qa2 << 20) | (qa3 << 21);
        }
    }
}

// ---------------- fused GEMM + softmax/match partial reduction ----------------
// 2-stage pipeline: per stage A 16KB + B 16KB = 32KB; 2 stages = 64KB/CTA.
// Two CTAs co-resident per SM. B fragments single-buffered (reg relief).
#define STAGE_BYTES (TM * KC * 2 + TN * KC * 2)
static constexpr int SMEM_BYTES = 2 * STAGE_BYTES + 1024;

__device__ __forceinline__ void issue_chunk(int it, int m0, int n0,
                                            uint32_t Ab, uint32_t Bb, int tid) {
    const uint4* ag = (const uint4*)g_abf;   // 128 uint4 per row
    const uint4* bg = (const uint4*)g_bbf;
    int k8 = it * (KC / 8);
#pragma unroll
    for (int u = 0; u < 4; u++) {            // A: 1024 16B chunks / 256 thr
        int idx = tid + u * NTHREADS;
        int row = idx >> 3, q = idx & 7;
        cpasync16(Ab + SW128(row * 128 + q * 16),
                  &ag[(size_t)(m0 + row) * 128 + k8 + q]);
    }
#pragma unroll
    for (int u = 0; u < 4; u++) {            // B: 1024 16B chunks / 256 thr
        int idx = tid + u * NTHREADS;
        int row = idx >> 3, q = idx & 7;
        cpasync16(Bb + SW128(row * 128 + q * 16),
                  &bg[(size_t)(n0 + row) * 128 + k8 + q]);
    }
    CP_COMMIT();
}

__global__ void __launch_bounds__(NTHREADS, 2) gemm_fused() {
    extern __shared__ char dsm[];
    char* base = (char*)(((uintptr_t)dsm + 1023) & ~(uintptr_t)1023);
    uint32_t sb = smem_u32(base);
    uint32_t Ab0 = sb, Ab1 = sb + STAGE_BYTES;
    uint32_t Bb0 = sb + TM * KC * 2, Bb1 = sb + STAGE_BYTES + TM * KC * 2;

    int tid = threadIdx.x;
    int wid = tid >> 5, lane = tid & 31;
    int m0 = blockIdx.y * TM, n0 = blockIdx.x * TN;
    int wm0 = (wid & 3) * 32;        // 4 m-warps, warp tile 32x64
    int wn0 = (wid >> 2) * 64;       // 2 n-warp groups

    float acc[2][8][4];
#pragma unroll
    for (int a = 0; a < 2; a++)
#pragma unroll
        for (int b = 0; b < 8; b++)
#pragma unroll
            for (int c = 0; c < 4; c++) acc[a][b][c] = 0.f;

    // Hoisted swizzle (k < 128 never reaches bit 7; xor term row-only)
    int akb = (lane >> 4) << 4;                       // 0 or 16
    int bkb = ((lane >> 3) & 1) << 4;                 // 0 or 16
    uint32_t a_base[2], b_base[4], a_swx[2], b_swx[4];
#pragma unroll
    for (int fm = 0; fm < 2; fm++) {
        uint32_t ro = (wm0 + fm * 16 + (lane & 15)) * 128;
        a_base[fm] = ro; a_swx[fm] = (ro >> 3) & 0x70;
    }
#pragma unroll
    for (int fn2 = 0; fn2 < 4; fn2++) {
        uint32_t ro = (wn0 + fn2 * 16 + (lane & 7) + ((lane >> 4) & 1) * 8) * 128;
        b_base[fn2] = ro; b_swx[fn2] = (ro >> 3) & 0x70;
    }

    issue_chunk(0, m0, n0, Ab0, Bb0, tid);
    CP_WAIT0();
    __syncthreads();

    for (int it = 0; it < NCHUNK; it++) {
        uint32_t Abc = (it & 1) ? Ab1 : Ab0;
        uint32_t Bbc = (it & 1) ? Bb1 : Bb0;
        if (it + 1 < NCHUNK)
            issue_chunk(it + 1, m0, n0, (it & 1) ? Ab0 : Ab1, (it & 1) ? Bb0 : Bb1, tid);

        // A double-buffered across ksteps; B single-buffered (reg relief)
        uint32_t af[2][2][4];
        ldmx4(af[0][0], Abc + a_base[0] + ((0 + akb) ^ a_swx[0]));
        ldmx4(af[0][1], Abc + a_base[1] + ((0 + akb) ^ a_swx[1]));
#pragma unroll
        for (int ks = 0; ks < 4; ks++) {
            int cur = ks & 1, nxt = cur ^ 1;
            uint32_t kb = ks * 32;
            uint32_t bf[4][4];
#pragma unroll
            for (int fn2 = 0; fn2 < 4; fn2++)
                ldmx4(bf[fn2], Bbc + b_base[fn2] + ((kb + bkb) ^ b_swx[fn2]));
            if (ks < 3) {
                uint32_t kb2 = kb + 32;
                ldmx4(af[nxt][0], Abc + a_base[0] + ((kb2 + akb) ^ a_swx[0]));
                ldmx4(af[nxt][1], Abc + a_base[1] + ((kb2 + akb) ^ a_swx[1]));
            }
#pragma unroll
            for (int fn2 = 0; fn2 < 4; fn2++) {
                mma16816(acc[0][2 * fn2 + 0], af[cur][0], bf[fn2][0], bf[fn2][1]);
                mma16816(acc[0][2 * fn2 + 1], af[cur][0], bf[fn2][2], bf[fn2][3]);
                mma16816(acc[1][2 * fn2 + 0], af[cur][1], bf[fn2][0], bf[fn2][1]);
                mma16816(acc[1][2 * fn2 + 1], af[cur][1], bf[fn2][2], bf[fn2][3]);
            }
        }
        if (it + 1 < NCHUNK) CP_WAIT0();
        __syncthreads();
    }

    // -------- epilogue: per-row 9-value partial reduction --------------------
    const float invT = 1.0f / 0.07f;
    const float LM = invT;          // analytic sim upper bound (unit vectors)

    int qv[16];
#pragma unroll
    for (int fn = 0; fn < 8; fn++)
#pragma unroll
        for (int e = 0; e < 2; e++)
            qv[fn * 2 + e] = g_qinfo[n0 + wn0 + fn * 8 + (lane & 3) * 2 + e];

    float* sacc = (float*)base;     // [2 n-warp-group][128 rows][9]
    int nw = wid >> 2;

#pragma unroll
    for (int fm = 0; fm < 2; fm++) {
#pragma unroll
        for (int half = 0; half < 2; half++) {
            int rlocal = wm0 + fm * 16 + half * 8 + (lane >> 2);
            int rglob = m0 + rlocal;
            int k1 = g_k1a[rglob];
            int a2f = g_act2[rglob], a3f = g_act3[rglob];
            int k2 = k1 >> 5, k3 = k1 >> 10;
            float S1 = 0.f, S2 = 0.f, S3 = 0.f;
            float P1 = 0.f, P2 = 0.f, P3 = 0.f;
            float c1 = 0.f, c2 = 0.f, c3 = 0.f;
#pragma unroll
            for (int fn = 0; fn < 8; fn++) {
#pragma unroll
                for (int e = 0; e < 2; e++) {
                    float s = acc[fm][fn][half * 2 + e] * invT;
                    float ex = __expf(s - LM);
                    int qi = qv[fn * 2 + e];
                    int qk = qi & 0xFFFF;
                    int qa2 = (qi >> 20) & 1, qa3 = (qi >> 21) & 1;
                    S1 += ex;
                    if (qa2) S2 += ex;
                    if (qa3) S3 += ex;
                    if (qk == k1) { P1 += s; c1 += 1.f; }
                    if (a2f && qa2 && ((qk >> 5) == k2)) { P2 += s; c2 += 1.f; }
                    if (a3f && qa3 && ((qk >> 10) == k3)) { P3 += s; c3 += 1.f; }
                }
            }
            float rs[9] = {S1, S2, S3, P1, P2, P3, c1, c2, c3};
#pragma unroll
            for (int v = 0; v < 9; v++) {
                rs[v] += __shfl_xor_sync(0xFFFFFFFFu, rs[v], 1);
                rs[v] += __shfl_xor_sync(0xFFFFFFFFu, rs[v], 2);
            }
            if ((lane & 3) == 0) {
#pragma unroll
                for (int v = 0; v < 9; v++)
                    sacc[((size_t)nw * 128 + rlocal) * 9 + v] = rs[v];
            }
        }
    }
    __syncthreads();

    for (int idx = tid; idx < 128 * 9; idx += NTHREADS) {
        int row = idx / 9, v = idx - row * 9;
        float sum = sacc[(size_t)row * 9 + v]
                  + sacc[(size_t)(128 + row) * 9 + v];
        g_part[((size_t)(m0 + row) * NT + blockIdx.x) * 9 + v] = sum;
    }
}

// ---------------- per-row final reduction ------------------------------------
__global__ void __launch_bounds__(256) row_reduce2() {
    int i = blockIdx.x;
    int t = threadIdx.x;          // one n-tile per thread (NT == 256)
    const float LM = 1.0f / 0.07f;
    float r[9];
    const float* p = &g_part[((size_t)i * NT + t) * 9];
#pragma unroll
    for (int v = 0; v < 9; v++) r[v] = p[v];
#pragma unroll
    for (int v = 0; v < 9; v++)
#pragma unroll
        for (int o = 16; o > 0; o >>= 1)
            r[v] += __shfl_xor_sync(0xFFFFFFFFu, r[v], o);

    __shared__ float wsum[8][9];
    int wid = t >> 5, lane = t & 31;
    if (lane == 0)
#pragma unroll
        for (int v = 0; v < 9; v++) wsum[wid][v] = r[v];
    __syncthreads();

    if (t == 0) {
        float res[9];
#pragma unroll
        for (int v = 0; v < 9; v++) {
            float acc = 0.f;
#pragma unroll
            for (int w = 0; w < 8; w++) acc += wsum[w][v];
            res[v] = acc;
        }
#pragma unroll
        for (int l = 0; l < 3; l++) {
            float S = res[l], P = res[3 + l], c = res[6 + l];
            float loss = 0.f;
            if (c > 0.f) loss = -(P - c * (LM + logf(S))) / (c + 1e-12f);
            g_rowloss[l][i] = loss;
            g_rowpos[l][i] = (c > 0.f) ? 1 : 0;
        }
    }
}

// ---------------- finalize ----------------------------------------------------
__global__ void __launch_bounds__(512) finalize(float* __restrict__ out) {
    __shared__ float sl[512];
    __shared__ float sn[512];
    __shared__ float layer[3];
    int t = threadIdx.x;
    for (int l = 0; l < 3; l++) {
        sl[t] = g_rowloss[l][t] + g_rowloss[l][t + 512];
        sn[t] = (float)(g_rowpos[l][t] + g_rowpos[l][t + 512]);
        __syncthreads();
        for (int s = 256; s > 0; s >>= 1) {
            if (t < s) { sl[t] += sl[t + s]; sn[t] += sn[t + s]; }
            __syncthreads();
        }
        if (t == 0) layer[l] = sl[0] / (sn[0] + 1e-12f);
        __syncthreads();
    }
    if (t == 0) {
        const float w[3] = {2.0f, 1.41421356237309515f, 1.25992104989487319f};
        float ml = -INFINITY, cum = 0.f;
#pragma unroll
        for (int l = 0; l < 3; l++) {
            float ll = fmaxf(ml, layer[l]);
            cum += w[l] * ll;
            ml = fmaxf(ml, ll);
        }
        out[0] = cum;
    }
}

// ---------------- launch ------------------------------------------------------
extern "C" void kernel_launch(void* const* d_in, const int* in_sizes, int n_in,
                              void* d_out, int out_size) {
    const float* f  = (const float*)d_in[0];
    const int*   la = (const int*)d_in[1];
    const float* fq = (const float*)d_in[2];
    const int*   lq = (const int*)d_in[3];
    float* out = (float*)d_out;

    static int attr_done = 0;
    if (!attr_done) {
        cudaFuncSetAttribute(gemm_fused, cudaFuncAttributeMaxDynamicSharedMemorySize,
                             SMEM_BYTES);
        attr_done = 1;
    }

    // order keeps gemm_fused in ncu's captured slot (-s 5 -c 1)
    conv_a<<<(BN * DN / 4) / 256, 256>>>(f);
    conv_b<<<(QN * DN / 4) / 256, 256>>>(fq);
    prep_all<<<1, BN>>>(la, lq);
    dim3 grid(QN / TN, BN / TM);
    gemm_fused<<<grid, NTHREADS, SMEM_BYTES>>>();
    row_reduce2<<<BN, 256>>>();
    finalize<<<1, 512>>>(out);
}

// round 16
// speedup vs baseline: 1.4635x; 1.4239x over previous
#include <cuda_runtime.h>
#include <cuda_bf16.h>
#include <math.h>
#include <stdint.h>

#define BN 1024
#define QN 32768
#define DN 1024
#define TM 128          // CTA M tile
#define TN 128          // CTA N tile
#define KC 64           // K chunk (bf16 elems) = 128 bytes per row
#define NCHUNK (DN / KC)
#define NT (QN / TN)    // 256 n-tiles
#define NTHREADS 256
#define NK1 20084       // max level-1 key + 1  (19*1024+19*32+19 = 20083)
#define NK2 628         // max level-2 key + 1  (20083 >> 5 = 627)

// ---------------- device scratch (static globals; no allocation) -------------
__device__ __nv_bfloat16 g_abf[(size_t)BN * DN];
__device__ __nv_bfloat16 g_bbf[(size_t)QN * DN];
__device__ int   g_k1a[BN];
__device__ unsigned char g_act2[BN];
__device__ unsigned char g_act3[BN];
__device__ int   g_qinfo[QN];
__device__ float g_part[(size_t)BN * NT * 9];
__device__ float g_rowloss[3][BN];
__device__ int   g_rowpos[3][BN];

// ---------------- small PTX helpers ------------------------------------------
__device__ __forceinline__ uint32_t smem_u32(const void* p) {
    uint32_t a;
    asm("{ .reg .u64 t; cvta.to.shared.u64 t, %1; cvt.u32.u64 %0, t; }" : "=r"(a) : "l"(p));
    return a;
}
#define SW128(o) ((o) ^ (((o) >> 3) & 0x70))

__device__ __forceinline__ void cpasync16(uint32_t dst, const void* src) {
    asm volatile("cp.async.cg.shared.global [%0], [%1], 16;" :: "r"(dst), "l"(src) : "memory");
}
#define CP_COMMIT() asm volatile("cp.async.commit_group;" ::: "memory")
#define CP_WAIT0()  asm volatile("cp.async.wait_group 0;" ::: "memory")

__device__ __forceinline__ void ldmx4(uint32_t* r, uint32_t addr) {
    asm volatile("ldmatrix.sync.aligned.m8n8.x4.shared.b16 {%0,%1,%2,%3}, [%4];"
                 : "=r"(r[0]), "=r"(r[1]), "=r"(r[2]), "=r"(r[3]) : "r"(addr));
}
__device__ __forceinline__ void mma16816(float* c, const uint32_t* a,
                                         uint32_t b0, uint32_t b1) {
    asm volatile(
        "mma.sync.aligned.m16n8k16.row.col.f32.bf16.bf16.f32 "
        "{%0,%1,%2,%3}, {%4,%5,%6,%7}, {%8,%9}, {%0,%1,%2,%3};"
        : "+f"(c[0]), "+f"(c[1]), "+f"(c[2]), "+f"(c[3])
        : "r"(a[0]), "r"(a[1]), "r"(a[2]), "r"(a[3]), "r"(b0), "r"(b1));
}

// ---------------- fp32 -> bf16 converters ------------------------------------
__global__ void conv_a(const float* __restrict__ in) {
    int i = blockIdx.x * blockDim.x + threadIdx.x;
    float4 v = __ldcs(&((const float4*)in)[i]);
    __nv_bfloat162 lo(__float2bfloat16(v.x), __float2bfloat16(v.y));
    __nv_bfloat162 hi(__float2bfloat16(v.z), __float2bfloat16(v.w));
    uint2 o; o.x = *(unsigned*)&lo; o.y = *(unsigned*)&hi;
    ((uint2*)g_abf)[i] = o;
}
__global__ void conv_b(const float* __restrict__ in) {
    int i = blockIdx.x * blockDim.x + threadIdx.x;
    float4 v = __ldcs(&((const float4*)in)[i]);
    __nv_bfloat162 lo(__float2bfloat16(v.x), __float2bfloat16(v.y));
    __nv_bfloat162 hi(__float2bfloat16(v.z), __float2bfloat16(v.w));
    uint2 o; o.x = *(unsigned*)&lo; o.y = *(unsigned*)&hi;
    ((uint2*)g_bbf)[i] = o;
}

// ---------------- combined anchor + queue prep (one block, O(B) atomics) ------
// last1[k1] = max anchor index with key k1  (torch unique keeps LAST occurrence)
// last2[k2] = max k1 among a2-kept anchors in group k2 (== max-rank survivor)
// presence sets fall out for free: pres1 <=> last1 >= 0, pres2 <=> last2 >= 0.
static constexpr int PREP_SMEM = (NK1 + NK2) * 4;

__global__ void prep_all(const int* __restrict__ labels, const int* __restrict__ lq) {
    extern __shared__ int psm[];
    int* last1 = psm;          // [NK1]
    int* last2 = psm + NK1;    // [NK2]
    int i = threadIdx.x;
    for (int t = i; t < NK1 + NK2; t += BN) psm[t] = -1;
    int4 L = ((const int4*)labels)[i];
    int k1 = L.x * 1024 + L.y * 32 + L.z;
    __syncthreads();

    atomicMax(&last1[k1], i);
    __syncthreads();
    bool a2 = (last1[k1] == i);
    if (a2) atomicMax(&last2[k1 >> 5], k1);
    __syncthreads();
    bool a3 = a2 && (last2[k1 >> 5] == k1);

    g_k1a[i] = k1;
    g_act2[i] = a2 ? 1 : 0;
    g_act3[i] = a3 ? 1 : 0;

    // queue info: active flags from presence arrays (smem, random LDS)
    for (int j = i; j < QN; j += BN) {
        int4 Q = ((const int4*)lq)[j];
        int qk = Q.x * 1024 + Q.y * 32 + Q.z;
        int qa2 = (last1[qk] < 0) ? 1 : 0;
        int qa3 = (qa2 && last2[qk >> 5] < 0) ? 1 : 0;
        g_qinfo[j] = qk | (qa2 << 20) | (qa3 << 21);
    }
}

// ---------------- fused GEMM + softmax/match partial reduction ----------------
// 2-stage pipeline: per stage A 16KB + B 16KB = 32KB; 2 stages = 64KB/CTA.
// Two CTAs co-resident per SM. B fragments single-buffered.
#define STAGE_BYTES (TM * KC * 2 + TN * KC * 2)
static constexpr int SMEM_BYTES = 2 * STAGE_BYTES + 1024;

__device__ __forceinline__ void issue_chunk(int it, int m0, int n0,
                                            uint32_t Ab, uint32_t Bb, int tid) {
    const uint4* ag = (const uint4*)g_abf;   // 128 uint4 per row
    const uint4* bg = (const uint4*)g_bbf;
    int k8 = it * (KC / 8);
#pragma unroll
    for (int u = 0; u < 4; u++) {            // A: 1024 16B chunks / 256 thr
        int idx = tid + u * NTHREADS;
        int row = idx >> 3, q = idx & 7;
        cpasync16(Ab + SW128(row * 128 + q * 16),
                  &ag[(size_t)(m0 + row) * 128 + k8 + q]);
    }
#pragma unroll
    for (int u = 0; u < 4; u++) {            // B: 1024 16B chunks / 256 thr
        int idx = tid + u * NTHREADS;
        int row = idx >> 3, q = idx & 7;
        cpasync16(Bb + SW128(row * 128 + q * 16),
                  &bg[(size_t)(n0 + row) * 128 + k8 + q]);
    }
    CP_COMMIT();
}

__global__ void __launch_bounds__(NTHREADS, 2) gemm_fused() {
    extern __shared__ char dsm[];
    char* base = (char*)(((uintptr_t)dsm + 1023) & ~(uintptr_t)1023);
    uint32_t sb = smem_u32(base);
    uint32_t Ab0 = sb, Ab1 = sb + STAGE_BYTES;
    uint32_t Bb0 = sb + TM * KC * 2, Bb1 = sb + STAGE_BYTES + TM * KC * 2;

    int tid = threadIdx.x;
    int wid = tid >> 5, lane = tid & 31;
    int m0 = blockIdx.y * TM, n0 = blockIdx.x * TN;
    int wm0 = (wid & 3) * 32;        // 4 m-warps, warp tile 32x64
    int wn0 = (wid >> 2) * 64;       // 2 n-warp groups

    float acc[2][8][4];
#pragma unroll
    for (int a = 0; a < 2; a++)
#pragma unroll
        for (int b = 0; b < 8; b++)
#pragma unroll
            for (int c = 0; c < 4; c++) acc[a][b][c] = 0.f;

    // Hoisted swizzle (k < 128 never reaches bit 7; xor term row-only)
    int akb = (lane >> 4) << 4;                       // 0 or 16
    int bkb = ((lane >> 3) & 1) << 4;                 // 0 or 16
    uint32_t a_base[2], b_base[4], a_swx[2], b_swx[4];
#pragma unroll
    for (int fm = 0; fm < 2; fm++) {
        uint32_t ro = (wm0 + fm * 16 + (lane & 15)) * 128;
        a_base[fm] = ro; a_swx[fm] = (ro >> 3) & 0x70;
    }
#pragma unroll
    for (int fn2 = 0; fn2 < 4; fn2++) {
        uint32_t ro = (wn0 + fn2 * 16 + (lane & 7) + ((lane >> 4) & 1) * 8) * 128;
        b_base[fn2] = ro; b_swx[fn2] = (ro >> 3) & 0x70;
    }

    issue_chunk(0, m0, n0, Ab0, Bb0, tid);
    CP_WAIT0();
    __syncthreads();

    for (int it = 0; it < NCHUNK; it++) {
        uint32_t Abc = (it & 1) ? Ab1 : Ab0;
        uint32_t Bbc = (it & 1) ? Bb1 : Bb0;
        if (it + 1 < NCHUNK)
            issue_chunk(it + 1, m0, n0, (it & 1) ? Ab0 : Ab1, (it & 1) ? Bb0 : Bb1, tid);

        // A double-buffered across ksteps; B single-buffered
        uint32_t af[2][2][4];
        ldmx4(af[0][0], Abc + a_base[0] + ((0 + akb) ^ a_swx[0]));
        ldmx4(af[0][1], Abc + a_base[1] + ((0 + akb) ^ a_swx[1]));
#pragma unroll
        for (int ks = 0; ks < 4; ks++) {
            int cur = ks & 1, nxt = cur ^ 1;
            uint32_t kb = ks * 32;
            uint32_t bf[4][4];
#pragma unroll
            for (int fn2 = 0; fn2 < 4; fn2++)
                ldmx4(bf[fn2], Bbc + b_base[fn2] + ((kb + bkb) ^ b_swx[fn2]));
            if (ks < 3) {
                uint32_t kb2 = kb + 32;
                ldmx4(af[nxt][0], Abc + a_base[0] + ((kb2 + akb) ^ a_swx[0]));
                ldmx4(af[nxt][1], Abc + a_base[1] + ((kb2 + akb) ^ a_swx[1]));
            }
#pragma unroll
            for (int fn2 = 0; fn2 < 4; fn2++) {
                mma16816(acc[0][2 * fn2 + 0], af[cur][0], bf[fn2][0], bf[fn2][1]);
                mma16816(acc[0][2 * fn2 + 1], af[cur][0], bf[fn2][2], bf[fn2][3]);
                mma16816(acc[1][2 * fn2 + 0], af[cur][1], bf[fn2][0], bf[fn2][1]);
                mma16816(acc[1][2 * fn2 + 1], af[cur][1], bf[fn2][2], bf[fn2][3]);
            }
        }
        if (it + 1 < NCHUNK) CP_WAIT0();
        __syncthreads();
    }

    // -------- epilogue: per-row 9-value partial reduction --------------------
    const float invT = 1.0f / 0.07f;
    const float LM = invT;          // analytic sim upper bound (unit vectors)

    int qv[16];
#pragma unroll
    for (int fn = 0; fn < 8; fn++)
#pragma unroll
        for (int e = 0; e < 2; e++)
            qv[fn * 2 + e] = g_qinfo[n0 + wn0 + fn * 8 + (lane & 3) * 2 + e];

    float* sacc = (float*)base;     // [2 n-warp-group][128 rows][9]
    int nw = wid >> 2;

#pragma unroll
    for (int fm = 0; fm < 2; fm++) {
#pragma unroll
        for (int half = 0; half < 2; half++) {
            int rlocal = wm0 + fm * 16 + half * 8 + (lane >> 2);
            int rglob = m0 + rlocal;
            int k1 = g_k1a[rglob];
            int a2f = g_act2[rglob], a3f = g_act3[rglob];
            int k2 = k1 >> 5, k3 = k1 >> 10;
            float S1 = 0.f, S2 = 0.f, S3 = 0.f;
            float P1 = 0.f, P2 = 0.f, P3 = 0.f;
            float c1 = 0.f, c2 = 0.f, c3 = 0.f;
#pragma unroll
            for (int fn = 0; fn < 8; fn++) {
#pragma unroll
                for (int e = 0; e < 2; e++) {
                    float s = acc[fm][fn][half * 2 + e] * invT;
                    float ex = __expf(s - LM);
                    int qi = qv[fn * 2 + e];
                    int qk = qi & 0xFFFF;
                    int qa2 = (qi >> 20) & 1, qa3 = (qi >> 21) & 1;
                    S1 += ex;
                    if (qa2) S2 += ex;
                    if (qa3) S3 += ex;
                    if (qk == k1) { P1 += s; c1 += 1.f; }
                    if (a2f && qa2 && ((qk >> 5) == k2)) { P2 += s; c2 += 1.f; }
                    if (a3f && qa3 && ((qk >> 10) == k3)) { P3 += s; c3 += 1.f; }
                }
            }
            float rs[9] = {S1, S2, S3, P1, P2, P3, c1, c2, c3};
#pragma unroll
            for (int v = 0; v < 9; v++) {
                rs[v] += __shfl_xor_sync(0xFFFFFFFFu, rs[v], 1);
                rs[v] += __shfl_xor_sync(0xFFFFFFFFu, rs[v], 2);
            }
            if ((lane & 3) == 0) {
#pragma unroll
                for (int v = 0; v < 9; v++)
                    sacc[((size_t)nw * 128 + rlocal) * 9 + v] = rs[v];
            }
        }
    }
    __syncthreads();

    for (int idx = tid; idx < 128 * 9; idx += NTHREADS) {
        int row = idx / 9, v = idx - row * 9;
        float sum = sacc[(size_t)row * 9 + v]
                  + sacc[(size_t)(128 + row) * 9 + v];
        g_part[((size_t)(m0 + row) * NT + blockIdx.x) * 9 + v] = sum;
    }
}

// ---------------- per-row final reduction ------------------------------------
__global__ void __launch_bounds__(256) row_reduce2() {
    int i = blockIdx.x;
    int t = threadIdx.x;          // one n-tile per thread (NT == 256)
    const float LM = 1.0f / 0.07f;
    float r[9];
    const float* p = &g_part[((size_t)i * NT + t) * 9];
#pragma unroll
    for (int v = 0; v < 9; v++) r[v] = p[v];
#pragma unroll
    for (int v = 0; v < 9; v++)
#pragma unroll
        for (int o = 16; o > 0; o >>= 1)
            r[v] += __shfl_xor_sync(0xFFFFFFFFu, r[v], o);

    __shared__ float wsum[8][9];
    int wid = t >> 5, lane = t & 31;
    if (lane == 0)
#pragma unroll
        for (int v = 0; v < 9; v++) wsum[wid][v] = r[v];
    __syncthreads();

    if (t == 0) {
        float res[9];
#pragma unroll
        for (int v = 0; v < 9; v++) {
            float acc = 0.f;
#pragma unroll
            for (int w = 0; w < 8; w++) acc += wsum[w][v];
            res[v] = acc;
        }
#pragma unroll
        for (int l = 0; l < 3; l++) {
            float S = res[l], P = res[3 + l], c = res[6 + l];
            float loss = 0.f;
            if (c > 0.f) loss = -(P - c * (LM + logf(S))) / (c + 1e-12f);
            g_rowloss[l][i] = loss;
            g_rowpos[l][i] = (c > 0.f) ? 1 : 0;
        }
    }
}

// ---------------- finalize ----------------------------------------------------
__global__ void __launch_bounds__(512) finalize(float* __restrict__ out) {
    __shared__ float sl[512];
    __shared__ float sn[512];
    __shared__ float layer[3];
    int t = threadIdx.x;
    for (int l = 0; l < 3; l++) {
        sl[t] = g_rowloss[l][t] + g_rowloss[l][t + 512];
        sn[t] = (float)(g_rowpos[l][t] + g_rowpos[l][t + 512]);
        __syncthreads();
        for (int s = 256; s > 0; s >>= 1) {
            if (t < s) { sl[t] += sl[t + s]; sn[t] += sn[t + s]; }
            __syncthreads();
        }
        if (t == 0) layer[l] = sl[0] / (sn[0] + 1e-12f);
        __syncthreads();
    }
    if (t == 0) {
        const float w[3] = {2.0f, 1.41421356237309515f, 1.25992104989487319f};
        float ml = -INFINITY, cum = 0.f;
#pragma unroll
        for (int l = 0; l < 3; l++) {
            float ll = fmaxf(ml, layer[l]);
            cum += w[l] * ll;
            ml = fmaxf(ml, ll);
        }
        out[0] = cum;
    }
}

// ---------------- launch ------------------------------------------------------
extern "C" void kernel_launch(void* const* d_in, const int* in_sizes, int n_in,
                              void* d_out, int out_size) {
    const float* f  = (const float*)d_in[0];
    const int*   la = (const int*)d_in[1];
    const float* fq = (const float*)d_in[2];
    const int*   lq = (const int*)d_in[3];
    float* out = (float*)d_out;

    static int attr_done = 0;
    if (!attr_done) {
        cudaFuncSetAttribute(gemm_fused, cudaFuncAttributeMaxDynamicSharedMemorySize,
                             SMEM_BYTES);
        cudaFuncSetAttribute(prep_all, cudaFuncAttributeMaxDynamicSharedMemorySize,
                             PREP_SMEM);
        attr_done = 1;
    }

    // order keeps gemm_fused in ncu's captured slot (-s 5 -c 1)
    conv_a<<<(BN * DN / 4) / 256, 256>>>(f);
    conv_b<<<(QN * DN / 4) / 256, 256>>>(fq);
    prep_all<<<1, BN, PREP_SMEM>>>(la, lq);
    dim3 grid(QN / TN, BN / TM);
    gemm_fused<<<grid, NTHREADS, SMEM_BYTES>>>();
    row_reduce2<<<BN, 256>>>();
    finalize<<<1, 512>>>(out);
}